// round 12
// baseline (speedup 1.0000x reference)
#include <cuda_runtime.h>
#include <math.h>

// Problem constants
#define Bsz  4
#define Tseq 2048
#define Cdim 1024
#define NH   16
#define NKV  4
#define HD   64

// ---------------------------------------------------------------------------
// Scratch (device globals: no allocations allowed)
// ---------------------------------------------------------------------------
__device__ float g_q[Bsz * NH  * Tseq * HD];   // [B,H,T,D]
__device__ float g_k[Bsz * NKV * Tseq * HD];   // [B,KVH,T,D]
__device__ float g_v[Bsz * NKV * Tseq * HD];   // [B,KVH,T,D]
__device__ float g_o[Bsz * Tseq * Cdim];       // [B,T,H*D] attention output

// ---------------------------------------------------------------------------
// GEMM: Out[m,n] = sum_k A[m,k] * W[n,k]   (A: [8192,1024], W: [N,1024])
// mode 0: scatter q -> g_q[B,H,T,D]
// mode 1: scatter kv -> g_k / g_v [B,KVH,T,D]
// mode 2: A := g_o, Out[m*C+n] = acc + bias[n]
// ---------------------------------------------------------------------------
#define GBM 128
#define GBN 64
#define GBK 16

__global__ __launch_bounds__(256)
void gemm_kernel(const float* __restrict__ A, const float* __restrict__ W,
                 const float* __restrict__ bias, float* __restrict__ Out,
                 int mode)
{
    __shared__ float As[GBM][GBK + 4];   // stride 20 floats
    __shared__ float Ws[GBK][GBN + 1];   // transposed tile [k][n], stride 65

    const int tid = threadIdx.x;
    const int tx = tid & 15;
    const int ty = tid >> 4;
    const int m0 = blockIdx.y * GBM;
    const int n0 = blockIdx.x * GBN;

    const float* Ap = (mode == 2) ? (const float*)g_o : A;

    float acc[8][4];
#pragma unroll
    for (int i = 0; i < 8; i++)
#pragma unroll
        for (int j = 0; j < 4; j++) acc[i][j] = 0.f;

    for (int k0 = 0; k0 < Cdim; k0 += GBK) {
        // Load A tile: 128x16 = 512 float4
#pragma unroll
        for (int it = 0; it < 2; it++) {
            int idx = tid + it * 256;
            int r  = idx >> 2;
            int kq = (idx & 3) * 4;
            float4 va = *(const float4*)&Ap[(m0 + r) * Cdim + k0 + kq];
            *(float4*)&As[r][kq] = va;
        }
        // Load W tile transposed: 64x16 = 256 float4
        {
            int c  = tid >> 2;
            int kq = (tid & 3) * 4;
            float4 vw = *(const float4*)&W[(n0 + c) * Cdim + k0 + kq];
            Ws[kq + 0][c] = vw.x;
            Ws[kq + 1][c] = vw.y;
            Ws[kq + 2][c] = vw.z;
            Ws[kq + 3][c] = vw.w;
        }
        __syncthreads();

#pragma unroll
        for (int kk = 0; kk < GBK; kk++) {
            float a[8], b[4];
#pragma unroll
            for (int i = 0; i < 8; i++) a[i] = As[ty * 8 + i][kk];
#pragma unroll
            for (int j = 0; j < 4; j++) b[j] = Ws[kk][tx * 4 + j];
#pragma unroll
            for (int i = 0; i < 8; i++)
#pragma unroll
                for (int j = 0; j < 4; j++) acc[i][j] += a[i] * b[j];
        }
        __syncthreads();
    }

    // Epilogue
#pragma unroll
    for (int i = 0; i < 8; i++) {
        int m = m0 + ty * 8 + i;
        int bb = m >> 11;            // batch
        int t  = m & (Tseq - 1);     // seq pos
#pragma unroll
        for (int j = 0; j < 4; j++) {
            int n = n0 + tx * 4 + j;
            float v = acc[i][j];
            if (mode == 2) {
                Out[m * Cdim + n] = v + bias[n];
            } else if (mode == 0) {
                int h = n >> 6, d = n & 63;
                g_q[(((bb * NH + h) * Tseq + t)) * HD + d] = v;
            } else {
                if (n < NKV * HD) {
                    int kvh = n >> 6, d = n & 63;
                    g_k[((bb * NKV + kvh) * Tseq + t) * HD + d] = v;
                } else {
                    int nn = n - NKV * HD;
                    int kvh = nn >> 6, d = nn & 63;
                    g_v[((bb * NKV + kvh) * Tseq + t) * HD + d] = v;
                }
            }
        }
    }
}

// ---------------------------------------------------------------------------
// Attention: full (non-causal) softmax with lower-triangular ALiBi bias.
// scores = (q.k + (s<=t ? slope_h*(s-t) : 0)) * D^-0.5
// Tile: 128 queries x 64 keys, 256 threads, 8x4 microtile, online softmax.
// ---------------------------------------------------------------------------
#define ABM 128
#define ABN 64
// smem floats: Qs 128*68 + Kst 64*65 + Vs 64*68 + Pr 128*68
#define Q_STR   68
#define K_STR   65
#define V_STR   68
#define P_STR   68
#define OFF_K   (ABM * Q_STR)
#define OFF_V   (OFF_K + HD * K_STR)
#define OFF_P   (OFF_V + ABN * V_STR)
#define ATTN_SMEM_FLOATS (OFF_P + ABM * P_STR)
#define ATTN_SMEM_BYTES  (ATTN_SMEM_FLOATS * 4)

__global__ __launch_bounds__(256)
void attn_kernel()
{
    extern __shared__ float sm[];
    float* Qs  = sm;            // [r][d]  stride 68
    float* Kst = sm + OFF_K;    // [d][c]  stride 65 (transposed)
    float* Vs  = sm + OFF_V;    // [s][d]  stride 68
    float* Pr  = sm + OFF_P;    // [r][s]  stride 68

    const int tid = threadIdx.x;
    const int tx = tid & 15;
    const int ty = tid >> 4;
    const int qtile = blockIdx.x;
    const int bh = blockIdx.y;
    const int b = bh >> 4;
    const int h = bh & 15;
    const int kvh = h & (NKV - 1);

    const float* Qp = g_q + ((size_t)(b * NH + h) * Tseq + qtile * ABM) * HD;
    const float* Kp = g_k + (size_t)(b * NKV + kvh) * Tseq * HD;
    const float* Vp = g_v + (size_t)(b * NKV + kvh) * Tseq * HD;

    const float slope  = exp2f(-0.5f * (float)(h + 1));
    const float iscale = 0.125f;  // 1/sqrt(64)

    // Load Q tile (128x64)
#pragma unroll
    for (int it = 0; it < 8; it++) {
        int idx = tid + it * 256;
        int r  = idx >> 4;
        int dq = (idx & 15) * 4;
        *(float4*)&Qs[r * Q_STR + dq] = *(const float4*)&Qp[r * HD + dq];
    }

    float o[8][4];
    float mrow[8], lrow[8];
#pragma unroll
    for (int i = 0; i < 8; i++) {
        mrow[i] = -1e30f;
        lrow[i] = 0.f;
#pragma unroll
        for (int j = 0; j < 4; j++) o[i][j] = 0.f;
    }

    const int rq0 = ty * 8;

    for (int s0 = 0; s0 < Tseq; s0 += ABN) {
        __syncthreads();  // previous PV done (and Q-load visible on first iter)

        // Load K tile transposed: Kst[d][c]
#pragma unroll
        for (int it = 0; it < 4; it++) {
            int idx = tid + it * 256;
            int c  = idx >> 4;
            int dq = (idx & 15) * 4;
            float4 v = *(const float4*)&Kp[(s0 + c) * HD + dq];
            Kst[(dq + 0) * K_STR + c] = v.x;
            Kst[(dq + 1) * K_STR + c] = v.y;
            Kst[(dq + 2) * K_STR + c] = v.z;
            Kst[(dq + 3) * K_STR + c] = v.w;
        }
        // Load V tile: Vs[s][d]
#pragma unroll
        for (int it = 0; it < 4; it++) {
            int idx = tid + it * 256;
            int s  = idx >> 4;
            int dq = (idx & 15) * 4;
            *(float4*)&Vs[s * V_STR + dq] = *(const float4*)&Vp[(s0 + s) * HD + dq];
        }
        __syncthreads();

        // S = Q K^T  (8x4 per thread)
        float sacc[8][4];
#pragma unroll
        for (int i = 0; i < 8; i++)
#pragma unroll
            for (int j = 0; j < 4; j++) sacc[i][j] = 0.f;

#pragma unroll 16
        for (int kk = 0; kk < HD; kk++) {
            float a[8], bf[4];
#pragma unroll
            for (int i = 0; i < 8; i++) a[i] = Qs[(rq0 + i) * Q_STR + kk];
#pragma unroll
            for (int j = 0; j < 4; j++) bf[j] = Kst[kk * K_STR + tx * 4 + j];
#pragma unroll
            for (int i = 0; i < 8; i++)
#pragma unroll
                for (int j = 0; j < 4; j++) sacc[i][j] += a[i] * bf[j];
        }

        // bias + online softmax (row stats shared by 16 lanes with same ty)
#pragma unroll
        for (int i = 0; i < 8; i++) {
            int tq = qtile * ABM + rq0 + i;
            float cmax = -1e30f;
#pragma unroll
            for (int j = 0; j < 4; j++) {
                int sk = s0 + tx * 4 + j;
                float bias = (sk <= tq) ? slope * (float)(sk - tq) : 0.f;
                float sv = (sacc[i][j] + bias) * iscale;
                sacc[i][j] = sv;
                cmax = fmaxf(cmax, sv);
            }
#pragma unroll
            for (int msk = 1; msk < 16; msk <<= 1)
                cmax = fmaxf(cmax, __shfl_xor_sync(0xffffffffu, cmax, msk));

            float mnew = fmaxf(mrow[i], cmax);
            float corr = __expf(mrow[i] - mnew);
            mrow[i] = mnew;

            float psum = 0.f;
#pragma unroll
            for (int j = 0; j < 4; j++) {
                float p = __expf(sacc[i][j] - mnew);
                sacc[i][j] = p;
                psum += p;
            }
#pragma unroll
            for (int msk = 1; msk < 16; msk <<= 1)
                psum += __shfl_xor_sync(0xffffffffu, psum, msk);

            lrow[i] = lrow[i] * corr + psum;
#pragma unroll
            for (int j = 0; j < 4; j++) o[i][j] *= corr;

            *(float4*)&Pr[(rq0 + i) * P_STR + tx * 4] =
                make_float4(sacc[i][0], sacc[i][1], sacc[i][2], sacc[i][3]);
        }
        __syncthreads();

        // O += P V
#pragma unroll 4
        for (int s = 0; s < ABN; s++) {
            float a[8];
#pragma unroll
            for (int i = 0; i < 8; i++) a[i] = Pr[(rq0 + i) * P_STR + s];
            float4 bv = *(const float4*)&Vs[s * V_STR + tx * 4];
#pragma unroll
            for (int i = 0; i < 8; i++) {
                o[i][0] += a[i] * bv.x;
                o[i][1] += a[i] * bv.y;
                o[i][2] += a[i] * bv.z;
                o[i][3] += a[i] * bv.w;
            }
        }
    }

    // Write output: g_o[b][t][h][d]
#pragma unroll
    for (int i = 0; i < 8; i++) {
        float inv = 1.f / lrow[i];
        int t = qtile * ABM + rq0 + i;
        float4 r = make_float4(o[i][0] * inv, o[i][1] * inv,
                               o[i][2] * inv, o[i][3] * inv);
        *(float4*)&g_o[(((size_t)b * Tseq + t) * NH + h) * HD + tx * 4] = r;
    }
}

// ---------------------------------------------------------------------------
// Launch
// ---------------------------------------------------------------------------
extern "C" void kernel_launch(void* const* d_in, const int* in_sizes, int n_in,
                              void* d_out, int out_size)
{
    (void)in_sizes; (void)n_in; (void)out_size;
    const float* x     = (const float*)d_in[0];
    const float* Wq    = (const float*)d_in[1];
    const float* Wkv   = (const float*)d_in[2];
    const float* Wproj = (const float*)d_in[3];
    const float* bproj = (const float*)d_in[4];
    float* out = (float*)d_out;

    cudaFuncSetAttribute(attn_kernel,
                         cudaFuncAttributeMaxDynamicSharedMemorySize,
                         ATTN_SMEM_BYTES);

    dim3 blk(256);
    const int MROWS = (Bsz * Tseq) / GBM;  // 64

    // Q projection: N = 1024
    gemm_kernel<<<dim3(Cdim / GBN, MROWS), blk>>>(x, Wq, nullptr, nullptr, 0);
    // KV projection: N = 512
    gemm_kernel<<<dim3((2 * NKV * HD) / GBN, MROWS), blk>>>(x, Wkv, nullptr, nullptr, 1);
    // Attention: 16 q-tiles x 64 (b,h)
    attn_kernel<<<dim3(Tseq / ABM, Bsz * NH), blk, ATTN_SMEM_BYTES>>>();
    // Output projection: N = 1024, + bias
    gemm_kernel<<<dim3(Cdim / GBN, MROWS), blk>>>(nullptr, Wproj, bproj, out, 2);
}

// round 13
// speedup vs baseline: 1.0004x; 1.0004x over previous
#include <cuda_runtime.h>
#include <math.h>

// Problem constants
#define Bsz  4
#define Tseq 2048
#define Cdim 1024
#define NH   16
#define NKV  4
#define HD   64

// ---------------------------------------------------------------------------
// Scratch (device globals: no allocations allowed)
// ---------------------------------------------------------------------------
__device__ float g_q[Bsz * NH  * Tseq * HD];   // [B,H,T,D]
__device__ float g_k[Bsz * NKV * Tseq * HD];   // [B,KVH,T,D]
__device__ float g_v[Bsz * NKV * Tseq * HD];   // [B,KVH,T,D]
__device__ float g_o[Bsz * Tseq * Cdim];       // [B,T,H*D] attention output

// ---------------------------------------------------------------------------
// GEMM: Out[m,n] = sum_k A[m,k] * W[n,k]   (A: [8192,1024], W: [N,1024])
// mode 0: scatter q -> g_q[B,H,T,D]
// mode 1: scatter kv -> g_k / g_v [B,KVH,T,D]
// mode 2: A := g_o, Out[m*C+n] = acc + bias[n]
// ---------------------------------------------------------------------------
#define GBM 128
#define GBN 64
#define GBK 16

__global__ __launch_bounds__(256)
void gemm_kernel(const float* __restrict__ A, const float* __restrict__ W,
                 const float* __restrict__ bias, float* __restrict__ Out,
                 int mode)
{
    __shared__ float As[GBM][GBK + 4];   // stride 20 floats
    __shared__ float Ws[GBK][GBN + 1];   // transposed tile [k][n], stride 65

    const int tid = threadIdx.x;
    const int tx = tid & 15;
    const int ty = tid >> 4;
    const int m0 = blockIdx.y * GBM;
    const int n0 = blockIdx.x * GBN;

    const float* Ap = (mode == 2) ? (const float*)g_o : A;

    float acc[8][4];
#pragma unroll
    for (int i = 0; i < 8; i++)
#pragma unroll
        for (int j = 0; j < 4; j++) acc[i][j] = 0.f;

    for (int k0 = 0; k0 < Cdim; k0 += GBK) {
        // Load A tile: 128x16 = 512 float4
#pragma unroll
        for (int it = 0; it < 2; it++) {
            int idx = tid + it * 256;
            int r  = idx >> 2;
            int kq = (idx & 3) * 4;
            float4 va = *(const float4*)&Ap[(m0 + r) * Cdim + k0 + kq];
            *(float4*)&As[r][kq] = va;
        }
        // Load W tile transposed: 64x16 = 256 float4
        {
            int c  = tid >> 2;
            int kq = (tid & 3) * 4;
            float4 vw = *(const float4*)&W[(n0 + c) * Cdim + k0 + kq];
            Ws[kq + 0][c] = vw.x;
            Ws[kq + 1][c] = vw.y;
            Ws[kq + 2][c] = vw.z;
            Ws[kq + 3][c] = vw.w;
        }
        __syncthreads();

#pragma unroll
        for (int kk = 0; kk < GBK; kk++) {
            float a[8], b[4];
#pragma unroll
            for (int i = 0; i < 8; i++) a[i] = As[ty * 8 + i][kk];
#pragma unroll
            for (int j = 0; j < 4; j++) b[j] = Ws[kk][tx * 4 + j];
#pragma unroll
            for (int i = 0; i < 8; i++)
#pragma unroll
                for (int j = 0; j < 4; j++) acc[i][j] += a[i] * b[j];
        }
        __syncthreads();
    }

    // Epilogue
#pragma unroll
    for (int i = 0; i < 8; i++) {
        int m = m0 + ty * 8 + i;
        int bb = m >> 11;            // batch
        int t  = m & (Tseq - 1);     // seq pos
#pragma unroll
        for (int j = 0; j < 4; j++) {
            int n = n0 + tx * 4 + j;
            float v = acc[i][j];
            if (mode == 2) {
                Out[m * Cdim + n] = v + bias[n];
            } else if (mode == 0) {
                int h = n >> 6, d = n & 63;
                g_q[(((bb * NH + h) * Tseq + t)) * HD + d] = v;
            } else {
                if (n < NKV * HD) {
                    int kvh = n >> 6, d = n & 63;
                    g_k[((bb * NKV + kvh) * Tseq + t) * HD + d] = v;
                } else {
                    int nn = n - NKV * HD;
                    int kvh = nn >> 6, d = nn & 63;
                    g_v[((bb * NKV + kvh) * Tseq + t) * HD + d] = v;
                }
            }
        }
    }
}

// ---------------------------------------------------------------------------
// Attention: full (non-causal) softmax with lower-triangular ALiBi bias.
// scores = (q.k + (s<=t ? slope_h*(s-t) : 0)) * D^-0.5
// Tile: 128 queries x 64 keys, 256 threads, 8x4 microtile, online softmax.
// ---------------------------------------------------------------------------
#define ABM 128
#define ABN 64
// smem floats: Qs 128*68 + Kst 64*65 + Vs 64*68 + Pr 128*68
#define Q_STR   68
#define K_STR   65
#define V_STR   68
#define P_STR   68
#define OFF_K   (ABM * Q_STR)
#define OFF_V   (OFF_K + HD * K_STR)
#define OFF_P   (OFF_V + ABN * V_STR)
#define ATTN_SMEM_FLOATS (OFF_P + ABM * P_STR)
#define ATTN_SMEM_BYTES  (ATTN_SMEM_FLOATS * 4)

__global__ __launch_bounds__(256)
void attn_kernel()
{
    extern __shared__ float sm[];
    float* Qs  = sm;            // [r][d]  stride 68
    float* Kst = sm + OFF_K;    // [d][c]  stride 65 (transposed)
    float* Vs  = sm + OFF_V;    // [s][d]  stride 68
    float* Pr  = sm + OFF_P;    // [r][s]  stride 68

    const int tid = threadIdx.x;
    const int tx = tid & 15;
    const int ty = tid >> 4;
    const int qtile = blockIdx.x;
    const int bh = blockIdx.y;
    const int b = bh >> 4;
    const int h = bh & 15;
    const int kvh = h & (NKV - 1);

    const float* Qp = g_q + ((size_t)(b * NH + h) * Tseq + qtile * ABM) * HD;
    const float* Kp = g_k + (size_t)(b * NKV + kvh) * Tseq * HD;
    const float* Vp = g_v + (size_t)(b * NKV + kvh) * Tseq * HD;

    const float slope  = exp2f(-0.5f * (float)(h + 1));
    const float iscale = 0.125f;  // 1/sqrt(64)

    // Load Q tile (128x64)
#pragma unroll
    for (int it = 0; it < 8; it++) {
        int idx = tid + it * 256;
        int r  = idx >> 4;
        int dq = (idx & 15) * 4;
        *(float4*)&Qs[r * Q_STR + dq] = *(const float4*)&Qp[r * HD + dq];
    }

    float o[8][4];
    float mrow[8], lrow[8];
#pragma unroll
    for (int i = 0; i < 8; i++) {
        mrow[i] = -1e30f;
        lrow[i] = 0.f;
#pragma unroll
        for (int j = 0; j < 4; j++) o[i][j] = 0.f;
    }

    const int rq0 = ty * 8;

    for (int s0 = 0; s0 < Tseq; s0 += ABN) {
        __syncthreads();  // previous PV done (and Q-load visible on first iter)

        // Load K tile transposed: Kst[d][c]
#pragma unroll
        for (int it = 0; it < 4; it++) {
            int idx = tid + it * 256;
            int c  = idx >> 4;
            int dq = (idx & 15) * 4;
            float4 v = *(const float4*)&Kp[(s0 + c) * HD + dq];
            Kst[(dq + 0) * K_STR + c] = v.x;
            Kst[(dq + 1) * K_STR + c] = v.y;
            Kst[(dq + 2) * K_STR + c] = v.z;
            Kst[(dq + 3) * K_STR + c] = v.w;
        }
        // Load V tile: Vs[s][d]
#pragma unroll
        for (int it = 0; it < 4; it++) {
            int idx = tid + it * 256;
            int s  = idx >> 4;
            int dq = (idx & 15) * 4;
            *(float4*)&Vs[s * V_STR + dq] = *(const float4*)&Vp[(s0 + s) * HD + dq];
        }
        __syncthreads();

        // S = Q K^T  (8x4 per thread)
        float sacc[8][4];
#pragma unroll
        for (int i = 0; i < 8; i++)
#pragma unroll
            for (int j = 0; j < 4; j++) sacc[i][j] = 0.f;

#pragma unroll 16
        for (int kk = 0; kk < HD; kk++) {
            float a[8], bf[4];
#pragma unroll
            for (int i = 0; i < 8; i++) a[i] = Qs[(rq0 + i) * Q_STR + kk];
#pragma unroll
            for (int j = 0; j < 4; j++) bf[j] = Kst[kk * K_STR + tx * 4 + j];
#pragma unroll
            for (int i = 0; i < 8; i++)
#pragma unroll
                for (int j = 0; j < 4; j++) sacc[i][j] += a[i] * bf[j];
        }

        // bias + online softmax (row stats shared by 16 lanes with same ty)
#pragma unroll
        for (int i = 0; i < 8; i++) {
            int tq = qtile * ABM + rq0 + i;
            float cmax = -1e30f;
#pragma unroll
            for (int j = 0; j < 4; j++) {
                int sk = s0 + tx * 4 + j;
                float bias = (sk <= tq) ? slope * (float)(sk - tq) : 0.f;
                float sv = (sacc[i][j] + bias) * iscale;
                sacc[i][j] = sv;
                cmax = fmaxf(cmax, sv);
            }
#pragma unroll
            for (int msk = 1; msk < 16; msk <<= 1)
                cmax = fmaxf(cmax, __shfl_xor_sync(0xffffffffu, cmax, msk));

            float mnew = fmaxf(mrow[i], cmax);
            float corr = __expf(mrow[i] - mnew);
            mrow[i] = mnew;

            float psum = 0.f;
#pragma unroll
            for (int j = 0; j < 4; j++) {
                float p = __expf(sacc[i][j] - mnew);
                sacc[i][j] = p;
                psum += p;
            }
#pragma unroll
            for (int msk = 1; msk < 16; msk <<= 1)
                psum += __shfl_xor_sync(0xffffffffu, psum, msk);

            lrow[i] = lrow[i] * corr + psum;
#pragma unroll
            for (int j = 0; j < 4; j++) o[i][j] *= corr;

            *(float4*)&Pr[(rq0 + i) * P_STR + tx * 4] =
                make_float4(sacc[i][0], sacc[i][1], sacc[i][2], sacc[i][3]);
        }
        __syncthreads();

        // O += P V
#pragma unroll 4
        for (int s = 0; s < ABN; s++) {
            float a[8];
#pragma unroll
            for (int i = 0; i < 8; i++) a[i] = Pr[(rq0 + i) * P_STR + s];
            float4 bv = *(const float4*)&Vs[s * V_STR + tx * 4];
#pragma unroll
            for (int i = 0; i < 8; i++) {
                o[i][0] += a[i] * bv.x;
                o[i][1] += a[i] * bv.y;
                o[i][2] += a[i] * bv.z;
                o[i][3] += a[i] * bv.w;
            }
        }
    }

    // Write output: g_o[b][t][h][d]
#pragma unroll
    for (int i = 0; i < 8; i++) {
        float inv = 1.f / lrow[i];
        int t = qtile * ABM + rq0 + i;
        float4 r = make_float4(o[i][0] * inv, o[i][1] * inv,
                               o[i][2] * inv, o[i][3] * inv);
        *(float4*)&g_o[(((size_t)b * Tseq + t) * NH + h) * HD + tx * 4] = r;
    }
}

// ---------------------------------------------------------------------------
// Launch
// ---------------------------------------------------------------------------
extern "C" void kernel_launch(void* const* d_in, const int* in_sizes, int n_in,
                              void* d_out, int out_size)
{
    (void)in_sizes; (void)n_in; (void)out_size;
    const float* x     = (const float*)d_in[0];
    const float* Wq    = (const float*)d_in[1];
    const float* Wkv   = (const float*)d_in[2];
    const float* Wproj = (const float*)d_in[3];
    const float* bproj = (const float*)d_in[4];
    float* out = (float*)d_out;

    cudaFuncSetAttribute(attn_kernel,
                         cudaFuncAttributeMaxDynamicSharedMemorySize,
                         ATTN_SMEM_BYTES);

    dim3 blk(256);
    const int MROWS = (Bsz * Tseq) / GBM;  // 64

    // Q projection: N = 1024
    gemm_kernel<<<dim3(Cdim / GBN, MROWS), blk>>>(x, Wq, nullptr, nullptr, 0);
    // KV projection: N = 512
    gemm_kernel<<<dim3((2 * NKV * HD) / GBN, MROWS), blk>>>(x, Wkv, nullptr, nullptr, 1);
    // Attention: 16 q-tiles x 64 (b,h)
    attn_kernel<<<dim3(Tseq / ABM, Bsz * NH), blk, ATTN_SMEM_BYTES>>>();
    // Output projection: N = 1024, + bias
    gemm_kernel<<<dim3(Cdim / GBN, MROWS), blk>>>(nullptr, Wproj, bproj, out, 2);
}

// round 17
// speedup vs baseline: 1.3764x; 1.3758x over previous
#include <cuda_runtime.h>
#include <cuda_bf16.h>
#include <cstdint>
#include <math.h>

// Problem constants
#define Bsz  4
#define Tseq 2048
#define Cdim 1024
#define NH   16
#define NKV  4
#define HD   64

// ---------------------------------------------------------------------------
// Scratch (device globals: no allocations allowed)
// ---------------------------------------------------------------------------
__device__ float g_q[Bsz * NH  * Tseq * HD];   // [B,H,T,D]
__device__ float g_k[Bsz * NKV * Tseq * HD];   // [B,KVH,T,D]
__device__ float g_v[Bsz * NKV * Tseq * HD];   // [B,KVH,T,D]
__device__ float g_o[Bsz * Tseq * Cdim];       // [B,T,H*D] attention output

// ---------------------------------------------------------------------------
// HMMA GEMM: Out[m,n] = sum_k A[m,k] * W[n,k]  via bf16 hi/lo split
// (3 MMAs per k-chunk: hi*hi + hi*lo + lo*hi; error ~eps_bf16^2 ~ 2e-5)
// Block tile 128x128, BK=64, 8 warps (2m x 4n), warp tile 64x32.
// mode 0: scatter q ; mode 1: scatter k/v ; mode 2: A=g_o, Out += bias
// ---------------------------------------------------------------------------
#define TBM 128
#define TBN 128
#define TBK 64
#define KSTEPS (Cdim / TBK)     // 16
#define TSTR 72                 // bf16 elems per smem row (64 + 8 pad)

#define SM_AH 0
#define SM_AL (SM_AH + TBM * TSTR * 2)   // 18432
#define SM_BH (SM_AL + TBM * TSTR * 2)
#define SM_BL (SM_BH + TBM * TSTR * 2)
#define GEMM_SMEM (SM_BL + TBM * TSTR * 2)   // 73728 bytes

__device__ __forceinline__ uint32_t smem_u32(const void* p) {
    uint32_t a;
    asm("{ .reg .u64 t; cvta.to.shared.u64 t, %1; cvt.u32.u64 %0, t; }"
        : "=r"(a) : "l"(p));
    return a;
}

__device__ __forceinline__ void ldmx4(uint32_t& d0, uint32_t& d1,
                                      uint32_t& d2, uint32_t& d3, uint32_t addr) {
    asm volatile("ldmatrix.sync.aligned.m8n8.x4.shared.b16 {%0,%1,%2,%3}, [%4];"
                 : "=r"(d0), "=r"(d1), "=r"(d2), "=r"(d3) : "r"(addr));
}

__device__ __forceinline__ void mma16816(float* c, const uint32_t* a,
                                         const uint32_t* b) {
    asm volatile(
        "mma.sync.aligned.m16n8k16.row.col.f32.bf16.bf16.f32 "
        "{%0,%1,%2,%3}, {%4,%5,%6,%7}, {%8,%9}, {%0,%1,%2,%3};"
        : "+f"(c[0]), "+f"(c[1]), "+f"(c[2]), "+f"(c[3])
        : "r"(a[0]), "r"(a[1]), "r"(a[2]), "r"(a[3]), "r"(b[0]), "r"(b[1]));
}

__device__ __forceinline__ void split_store(char* hi, char* lo,
                                            uint32_t eoff, float4 v) {
    __nv_bfloat16 h0 = __float2bfloat16(v.x);
    __nv_bfloat16 h1 = __float2bfloat16(v.y);
    __nv_bfloat16 h2 = __float2bfloat16(v.z);
    __nv_bfloat16 h3 = __float2bfloat16(v.w);
    __nv_bfloat16 l0 = __float2bfloat16(v.x - __bfloat162float(h0));
    __nv_bfloat16 l1 = __float2bfloat16(v.y - __bfloat162float(h1));
    __nv_bfloat16 l2 = __float2bfloat16(v.z - __bfloat162float(h2));
    __nv_bfloat16 l3 = __float2bfloat16(v.w - __bfloat162float(h3));
    uint2 hp, lp;
    hp.x = (uint32_t)__bfloat16_as_ushort(h0) | ((uint32_t)__bfloat16_as_ushort(h1) << 16);
    hp.y = (uint32_t)__bfloat16_as_ushort(h2) | ((uint32_t)__bfloat16_as_ushort(h3) << 16);
    lp.x = (uint32_t)__bfloat16_as_ushort(l0) | ((uint32_t)__bfloat16_as_ushort(l1) << 16);
    lp.y = (uint32_t)__bfloat16_as_ushort(l2) | ((uint32_t)__bfloat16_as_ushort(l3) << 16);
    *(uint2*)(hi + eoff * 2) = hp;
    *(uint2*)(lo + eoff * 2) = lp;
}

__global__ __launch_bounds__(256)
void gemm_hmma(const float* __restrict__ A, const float* __restrict__ W,
               const float* __restrict__ bias, float* __restrict__ Out, int mode)
{
    extern __shared__ char sm[];
    const uint32_t smb = smem_u32(sm);
    const int tid  = threadIdx.x;
    const int wid  = tid >> 5;
    const int lane = tid & 31;
    const int wm = wid >> 2;          // 0..1 (m)
    const int wn = wid & 3;           // 0..3 (n)
    const int m0 = blockIdx.y * TBM;
    const int n0 = blockIdx.x * TBN;

    const float* Ap = (mode == 2) ? (const float*)g_o : A;

    float acc[4][4][4];
#pragma unroll
    for (int i = 0; i < 4; i++)
#pragma unroll
        for (int j = 0; j < 4; j++)
#pragma unroll
            for (int r = 0; r < 4; r++) acc[i][j][r] = 0.f;

    // ldmatrix lane-address components (constant across k-loop)
    // A x4: rows m0-15 (lane&15), k halves by lane>=16
    const uint32_t a_row = wm * 64 + (lane & 15);
    const uint32_t a_koff = (lane >> 4) << 3;
    // B x4: n16 block -> two n8 frags; lanes0-7:n0-7 k0, 8-15:n0-7 k8,
    //       16-23:n8-15 k0, 24-31:n8-15 k8
    const uint32_t b_row = wn * 32 + (lane & 7) + (((lane >> 4) & 1) << 3);
    const uint32_t b_koff = ((lane >> 3) & 1) << 3;

    for (int kt = 0; kt < KSTEPS; kt++) {
        const int k0 = kt * TBK;

        // Load + split A and B tiles: 128 rows x 64 fp32 each
#pragma unroll
        for (int it = 0; it < 8; it++) {
            int idx = tid + it * 256;
            int r = idx >> 4, q = idx & 15;
            float4 va = *(const float4*)&Ap[(size_t)(m0 + r) * Cdim + k0 + q * 4];
            split_store(sm + SM_AH, sm + SM_AL, (uint32_t)(r * TSTR + q * 4), va);
            float4 vw = *(const float4*)&W[(size_t)(n0 + r) * Cdim + k0 + q * 4];
            split_store(sm + SM_BH, sm + SM_BL, (uint32_t)(r * TSTR + q * 4), vw);
        }
        __syncthreads();

#pragma unroll
        for (int ks = 0; ks < 4; ks++) {
            const uint32_t akc = ks * 16 + a_koff;
            const uint32_t bkc = ks * 16 + b_koff;

            uint32_t af[4][4], bf[4][2];
            // A hi frags (4 m-tiles)
#pragma unroll
            for (int i = 0; i < 4; i++)
                ldmx4(af[i][0], af[i][1], af[i][2], af[i][3],
                      smb + SM_AH + ((a_row + i * 16) * TSTR + akc) * 2);
            // B hi frags (4 n-tiles via 2 x4 loads)
#pragma unroll
            for (int j2 = 0; j2 < 2; j2++)
                ldmx4(bf[j2 * 2][0], bf[j2 * 2][1], bf[j2 * 2 + 1][0], bf[j2 * 2 + 1][1],
                      smb + SM_BH + ((b_row + j2 * 16) * TSTR + bkc) * 2);
            // hi * hi
#pragma unroll
            for (int i = 0; i < 4; i++)
#pragma unroll
                for (int j = 0; j < 4; j++) mma16816(acc[i][j], af[i], bf[j]);

            // B lo frags -> hi * lo
            uint32_t bl[4][2];
#pragma unroll
            for (int j2 = 0; j2 < 2; j2++)
                ldmx4(bl[j2 * 2][0], bl[j2 * 2][1], bl[j2 * 2 + 1][0], bl[j2 * 2 + 1][1],
                      smb + SM_BL + ((b_row + j2 * 16) * TSTR + bkc) * 2);
#pragma unroll
            for (int i = 0; i < 4; i++)
#pragma unroll
                for (int j = 0; j < 4; j++) mma16816(acc[i][j], af[i], bl[j]);

            // A lo frags -> lo * hi
#pragma unroll
            for (int i = 0; i < 4; i++)
                ldmx4(af[i][0], af[i][1], af[i][2], af[i][3],
                      smb + SM_AL + ((a_row + i * 16) * TSTR + akc) * 2);
#pragma unroll
            for (int i = 0; i < 4; i++)
#pragma unroll
                for (int j = 0; j < 4; j++) mma16816(acc[i][j], af[i], bf[j]);
        }
        __syncthreads();
    }

    // ---------------- Epilogue: scatter ----------------
    // acc[i][j]: m = m0 + wm*64 + i*16 + lane/4 (+8 for regs 2,3)
    //            n = n0 + wn*32 + j*8 + (lane%4)*2 (+1 for odd reg)
#pragma unroll
    for (int i = 0; i < 4; i++) {
#pragma unroll
        for (int half = 0; half < 2; half++) {
            int m = m0 + wm * 64 + i * 16 + (lane >> 2) + half * 8;
            int bb = m >> 11;
            int t  = m & (Tseq - 1);
#pragma unroll
            for (int j = 0; j < 4; j++) {
                int n = n0 + wn * 32 + j * 8 + (lane & 3) * 2;
                float2 v = make_float2(acc[i][j][half * 2], acc[i][j][half * 2 + 1]);
                if (mode == 2) {
                    v.x += bias[n];
                    v.y += bias[n + 1];
                    *(float2*)&Out[(size_t)m * Cdim + n] = v;
                } else if (mode == 0) {
                    int h = n >> 6, d = n & 63;
                    *(float2*)&g_q[((size_t)(bb * NH + h) * Tseq + t) * HD + d] = v;
                } else {
                    if (n < NKV * HD) {
                        int kvh = n >> 6, d = n & 63;
                        *(float2*)&g_k[((size_t)(bb * NKV + kvh) * Tseq + t) * HD + d] = v;
                    } else {
                        int nn = n - NKV * HD;
                        int kvh = nn >> 6, d = nn & 63;
                        *(float2*)&g_v[((size_t)(bb * NKV + kvh) * Tseq + t) * HD + d] = v;
                    }
                }
            }
        }
    }
}

// ---------------------------------------------------------------------------
// Attention: full (non-causal) softmax with lower-triangular ALiBi bias.
// (unchanged from R13 passing version — fp32 FFMA)
// ---------------------------------------------------------------------------
#define ABM 128
#define ABN 64
#define Q_STR   68
#define K_STR   65
#define V_STR   68
#define P_STR   68
#define OFF_K   (ABM * Q_STR)
#define OFF_V   (OFF_K + HD * K_STR)
#define OFF_P   (OFF_V + ABN * V_STR)
#define ATTN_SMEM_FLOATS (OFF_P + ABM * P_STR)
#define ATTN_SMEM_BYTES  (ATTN_SMEM_FLOATS * 4)

__global__ __launch_bounds__(256)
void attn_kernel()
{
    extern __shared__ float smf[];
    float* Qs  = smf;
    float* Kst = smf + OFF_K;
    float* Vs  = smf + OFF_V;
    float* Pr  = smf + OFF_P;

    const int tid = threadIdx.x;
    const int tx = tid & 15;
    const int ty = tid >> 4;
    const int qtile = blockIdx.x;
    const int bh = blockIdx.y;
    const int b = bh >> 4;
    const int h = bh & 15;
    const int kvh = h & (NKV - 1);

    const float* Qp = g_q + ((size_t)(b * NH + h) * Tseq + qtile * ABM) * HD;
    const float* Kp = g_k + (size_t)(b * NKV + kvh) * Tseq * HD;
    const float* Vp = g_v + (size_t)(b * NKV + kvh) * Tseq * HD;

    const float slope  = exp2f(-0.5f * (float)(h + 1));
    const float iscale = 0.125f;

#pragma unroll
    for (int it = 0; it < 8; it++) {
        int idx = tid + it * 256;
        int r  = idx >> 4;
        int dq = (idx & 15) * 4;
        *(float4*)&Qs[r * Q_STR + dq] = *(const float4*)&Qp[r * HD + dq];
    }

    float o[8][4];
    float mrow[8], lrow[8];
#pragma unroll
    for (int i = 0; i < 8; i++) {
        mrow[i] = -1e30f;
        lrow[i] = 0.f;
#pragma unroll
        for (int j = 0; j < 4; j++) o[i][j] = 0.f;
    }

    const int rq0 = ty * 8;

    for (int s0 = 0; s0 < Tseq; s0 += ABN) {
        __syncthreads();

#pragma unroll
        for (int it = 0; it < 4; it++) {
            int idx = tid + it * 256;
            int c  = idx >> 4;
            int dq = (idx & 15) * 4;
            float4 v = *(const float4*)&Kp[(s0 + c) * HD + dq];
            Kst[(dq + 0) * K_STR + c] = v.x;
            Kst[(dq + 1) * K_STR + c] = v.y;
            Kst[(dq + 2) * K_STR + c] = v.z;
            Kst[(dq + 3) * K_STR + c] = v.w;
        }
#pragma unroll
        for (int it = 0; it < 4; it++) {
            int idx = tid + it * 256;
            int s  = idx >> 4;
            int dq = (idx & 15) * 4;
            *(float4*)&Vs[s * V_STR + dq] = *(const float4*)&Vp[(s0 + s) * HD + dq];
        }
        __syncthreads();

        float sacc[8][4];
#pragma unroll
        for (int i = 0; i < 8; i++)
#pragma unroll
            for (int j = 0; j < 4; j++) sacc[i][j] = 0.f;

#pragma unroll 16
        for (int kk = 0; kk < HD; kk++) {
            float a[8], bf[4];
#pragma unroll
            for (int i = 0; i < 8; i++) a[i] = Qs[(rq0 + i) * Q_STR + kk];
#pragma unroll
            for (int j = 0; j < 4; j++) bf[j] = Kst[kk * K_STR + tx * 4 + j];
#pragma unroll
            for (int i = 0; i < 8; i++)
#pragma unroll
                for (int j = 0; j < 4; j++) sacc[i][j] += a[i] * bf[j];
        }

#pragma unroll
        for (int i = 0; i < 8; i++) {
            int tq = qtile * ABM + rq0 + i;
            float cmax = -1e30f;
#pragma unroll
            for (int j = 0; j < 4; j++) {
                int sk = s0 + tx * 4 + j;
                float bias = (sk <= tq) ? slope * (float)(sk - tq) : 0.f;
                float sv = (sacc[i][j] + bias) * iscale;
                sacc[i][j] = sv;
                cmax = fmaxf(cmax, sv);
            }
#pragma unroll
            for (int msk = 1; msk < 16; msk <<= 1)
                cmax = fmaxf(cmax, __shfl_xor_sync(0xffffffffu, cmax, msk));

            float mnew = fmaxf(mrow[i], cmax);
            float corr = __expf(mrow[i] - mnew);
            mrow[i] = mnew;

            float psum = 0.f;
#pragma unroll
            for (int j = 0; j < 4; j++) {
                float p = __expf(sacc[i][j] - mnew);
                sacc[i][j] = p;
                psum += p;
            }
#pragma unroll
            for (int msk = 1; msk < 16; msk <<= 1)
                psum += __shfl_xor_sync(0xffffffffu, psum, msk);

            lrow[i] = lrow[i] * corr + psum;
#pragma unroll
            for (int j = 0; j < 4; j++) o[i][j] *= corr;

            *(float4*)&Pr[(rq0 + i) * P_STR + tx * 4] =
                make_float4(sacc[i][0], sacc[i][1], sacc[i][2], sacc[i][3]);
        }
        __syncthreads();

#pragma unroll 4
        for (int s = 0; s < ABN; s++) {
            float a[8];
#pragma unroll
            for (int i = 0; i < 8; i++) a[i] = Pr[(rq0 + i) * P_STR + s];
            float4 bv = *(const float4*)&Vs[s * V_STR + tx * 4];
#pragma unroll
            for (int i = 0; i < 8; i++) {
                o[i][0] += a[i] * bv.x;
                o[i][1] += a[i] * bv.y;
                o[i][2] += a[i] * bv.z;
                o[i][3] += a[i] * bv.w;
            }
        }
    }

#pragma unroll
    for (int i = 0; i < 8; i++) {
        float inv = 1.f / lrow[i];
        int t = qtile * ABM + rq0 + i;
        float4 r = make_float4(o[i][0] * inv, o[i][1] * inv,
                               o[i][2] * inv, o[i][3] * inv);
        *(float4*)&g_o[(((size_t)b * Tseq + t) * NH + h) * HD + tx * 4] = r;
    }
}

// ---------------------------------------------------------------------------
// Launch
// ---------------------------------------------------------------------------
extern "C" void kernel_launch(void* const* d_in, const int* in_sizes, int n_in,
                              void* d_out, int out_size)
{
    (void)in_sizes; (void)n_in; (void)out_size;
    const float* x     = (const float*)d_in[0];
    const float* Wq    = (const float*)d_in[1];
    const float* Wkv   = (const float*)d_in[2];
    const float* Wproj = (const float*)d_in[3];
    const float* bproj = (const float*)d_in[4];
    float* out = (float*)d_out;

    cudaFuncSetAttribute(gemm_hmma,
                         cudaFuncAttributeMaxDynamicSharedMemorySize, GEMM_SMEM);
    cudaFuncSetAttribute(attn_kernel,
                         cudaFuncAttributeMaxDynamicSharedMemorySize, ATTN_SMEM_BYTES);

    dim3 blk(256);
    const int MROWS = (Bsz * Tseq) / TBM;   // 64

    // Q projection: N = 1024
    gemm_hmma<<<dim3(Cdim / TBN, MROWS), blk, GEMM_SMEM>>>(x, Wq, nullptr, nullptr, 0);
    // KV projection: N = 512
    gemm_hmma<<<dim3((2 * NKV * HD) / TBN, MROWS), blk, GEMM_SMEM>>>(x, Wkv, nullptr, nullptr, 1);
    // Attention: 16 q-tiles x 64 (b,h)
    attn_kernel<<<dim3(Tseq / ABM, Bsz * NH), blk, ATTN_SMEM_BYTES>>>();
    // Output projection: N = 1024, + bias
    gemm_hmma<<<dim3(Cdim / TBN, MROWS), blk, GEMM_SMEM>>>(nullptr, Wproj, bproj, out, 2);
}